// round 1
// baseline (speedup 1.0000x reference)
#include <cuda_runtime.h>
#include <cstdint>

// ScaledDotProductAttention: B=2,H=16,S=2048,D=64 fp32, TEMPERATURE=32.
// Outputs (concatenated in d_out): output [2,16,2048,64], attention [2,16,2048,2048].
//
// Fused kernel, one CTA per (bh, q_tile=128):
//   pass 1: S = (Q/32) K^T via mma.sync tf32, rowsum += exp(S) (masked)
//   pass 2: recompute S, P = exp(S)/rowsum, write attention (fp32, 32B sectors),
//           stage P (tf32) in smem, O += P V via mma.sync tf32.
// No atomics, no global scratch -> deterministic and graph-capturable.

#define S_LEN 2048
#define D_DIM 64
#define QT    128          // q rows per CTA
#define NT    128          // key cols per k-tile
#define KTILES (S_LEN / NT)
#define QSTR  68           // padded stride for 64-wide fp32 tiles
#define PSTR  132          // padded stride for 128-wide P tile

#define SMEM_FLOATS (QT*QSTR*3 + QT*PSTR + 256 + 128)
#define SMEM_BYTES  (SMEM_FLOATS * 4)

__device__ __forceinline__ float to_tf32(float x) {
    uint32_t u;
    asm("cvt.rna.tf32.f32 %0, %1;" : "=r"(u) : "f"(x));
    return __uint_as_float(u);
}

__device__ __forceinline__ void mma8(float c[4], const uint32_t a[4], const uint32_t b[2]) {
    asm volatile(
        "mma.sync.aligned.m16n8k8.row.col.f32.tf32.tf32.f32 "
        "{%0,%1,%2,%3}, {%4,%5,%6,%7}, {%8,%9}, {%0,%1,%2,%3};\n"
        : "+f"(c[0]), "+f"(c[1]), "+f"(c[2]), "+f"(c[3])
        : "r"(a[0]), "r"(a[1]), "r"(a[2]), "r"(a[3]),
          "r"(b[0]), "r"(b[1]));
}

__global__ __launch_bounds__(256, 1)
void attn_fused(const float* __restrict__ q, const float* __restrict__ kg,
                const float* __restrict__ vg, const int* __restrict__ mask,
                float* __restrict__ out, float* __restrict__ attn) {
    extern __shared__ float smf[];
    float* qs     = smf;                    // [128][68] tf32 (Q/32)
    float* ks     = qs + QT * QSTR;         // [128][68] tf32 K tile
    float* vs     = ks + NT * QSTR;         // [128][68] tf32 V tile
    float* ps     = vs + NT * QSTR;         // [128][132] tf32 P tile
    float* rowsum = ps + QT * PSTR;         // [256]: two partials per row
    int*   msk    = (int*)(rowsum + 256);   // [128]

    const int tid  = threadIdx.x;
    const int lane = tid & 31;
    const int w    = tid >> 5;
    const int wm   = w >> 1;        // 0..3 (m block of 32 rows)
    const int wn   = w & 1;         // 0..1 (n block of 64 cols)
    const int g    = lane >> 2;     // 0..7
    const int cq   = lane & 3;      // 0..3

    const int qt = blockIdx.x;      // 0..15
    const int bh = blockIdx.y;      // 0..31
    const int b  = bh >> 4;
    const int q0 = qt * QT;

    const float* qbase = q  + ((long)bh * S_LEN + q0) * D_DIM;
    const float* kbase = kg + (long)bh * S_LEN * D_DIM;
    const float* vbase = vg + (long)bh * S_LEN * D_DIM;
    const int*   mbase = mask + (long)b * S_LEN;
    float* obase = out + ((long)bh * S_LEN + q0) * D_DIM;
    float* abase = attn ? attn + ((long)bh * S_LEN + q0) * (long)S_LEN : nullptr;

    // ---- load Q tile (scaled 1/32, rna->tf32) ----
    {
        const float4* src = reinterpret_cast<const float4*>(qbase);
        #pragma unroll
        for (int i = 0; i < 8; i++) {
            int idx = tid + i * 256;           // 2048 float4 = 128x64
            float4 val = src[idx];
            val.x = to_tf32(val.x * 0.03125f);
            val.y = to_tf32(val.y * 0.03125f);
            val.z = to_tf32(val.z * 0.03125f);
            val.w = to_tf32(val.w * 0.03125f);
            int row = idx >> 4, c4 = (idx & 15) << 2;
            *reinterpret_cast<float4*>(qs + row * QSTR + c4) = val;
        }
    }
    if (tid < 256) rowsum[tid] = 0.0f;

    // =========================== PASS 1: row sums ===========================
    float rs[2][2] = {{0.f, 0.f}, {0.f, 0.f}};
    for (int kt = 0; kt < KTILES; kt++) {
        __syncthreads();
        {
            const float4* src = reinterpret_cast<const float4*>(kbase + (long)kt * NT * D_DIM);
            #pragma unroll
            for (int i = 0; i < 8; i++) {
                int idx = tid + i * 256;
                float4 val = src[idx];
                val.x = to_tf32(val.x); val.y = to_tf32(val.y);
                val.z = to_tf32(val.z); val.w = to_tf32(val.w);
                int row = idx >> 4, c4 = (idx & 15) << 2;
                *reinterpret_cast<float4*>(ks + row * QSTR + c4) = val;
            }
            if (tid < NT) msk[tid] = mbase[kt * NT + tid];
        }
        __syncthreads();

        float c[2][8][4];
        #pragma unroll
        for (int mi = 0; mi < 2; mi++)
            #pragma unroll
            for (int ni = 0; ni < 8; ni++)
                #pragma unroll
                for (int r = 0; r < 4; r++) c[mi][ni][r] = 0.f;

        #pragma unroll
        for (int kk = 0; kk < 64; kk += 8) {
            uint32_t bf[8][2];
            #pragma unroll
            for (int ni = 0; ni < 8; ni++) {
                int nr = wn * 64 + ni * 8 + g;
                bf[ni][0] = __float_as_uint(ks[nr * QSTR + kk + cq]);
                bf[ni][1] = __float_as_uint(ks[nr * QSTR + kk + 4 + cq]);
            }
            #pragma unroll
            for (int mi = 0; mi < 2; mi++) {
                int mr = wm * 32 + mi * 16;
                uint32_t a[4];
                a[0] = __float_as_uint(qs[(mr + g)     * QSTR + kk + cq]);
                a[1] = __float_as_uint(qs[(mr + g + 8) * QSTR + kk + cq]);
                a[2] = __float_as_uint(qs[(mr + g)     * QSTR + kk + 4 + cq]);
                a[3] = __float_as_uint(qs[(mr + g + 8) * QSTR + kk + 4 + cq]);
                #pragma unroll
                for (int ni = 0; ni < 8; ni++) mma8(c[mi][ni], a, bf[ni]);
            }
        }

        #pragma unroll
        for (int mi = 0; mi < 2; mi++)
            #pragma unroll
            for (int ni = 0; ni < 8; ni++) {
                int col = wn * 64 + ni * 8 + 2 * cq;
                int m0 = msk[col], m1 = msk[col + 1];
                float e0 = m0 ? __expf(c[mi][ni][0]) : 0.f;
                float e1 = m1 ? __expf(c[mi][ni][1]) : 0.f;
                float e2 = m0 ? __expf(c[mi][ni][2]) : 0.f;
                float e3 = m1 ? __expf(c[mi][ni][3]) : 0.f;
                rs[mi][0] += e0 + e1;
                rs[mi][1] += e2 + e3;
            }
    }

    // deterministic cross-lane/warp reduction of row sums
    #pragma unroll
    for (int mi = 0; mi < 2; mi++)
        #pragma unroll
        for (int h = 0; h < 2; h++) {
            float s = rs[mi][h];
            s += __shfl_xor_sync(0xffffffffu, s, 1);
            s += __shfl_xor_sync(0xffffffffu, s, 2);
            if (cq == 0) rowsum[wn * 128 + wm * 32 + mi * 16 + h * 8 + g] = s;
        }
    __syncthreads();
    if (tid < QT) rowsum[tid] = 1.0f / (rowsum[tid] + rowsum[128 + tid]);
    __syncthreads();

    float inv[2][2];
    #pragma unroll
    for (int mi = 0; mi < 2; mi++)
        #pragma unroll
        for (int h = 0; h < 2; h++)
            inv[mi][h] = rowsum[wm * 32 + mi * 16 + h * 8 + g];

    // ================== PASS 2: attention write + O = P V ==================
    float o[2][4][4];
    #pragma unroll
    for (int mi = 0; mi < 2; mi++)
        #pragma unroll
        for (int ni = 0; ni < 4; ni++)
            #pragma unroll
            for (int r = 0; r < 4; r++) o[mi][ni][r] = 0.f;

    for (int kt = 0; kt < KTILES; kt++) {
        __syncthreads();
        {
            const float4* srck = reinterpret_cast<const float4*>(kbase + (long)kt * NT * D_DIM);
            const float4* srcv = reinterpret_cast<const float4*>(vbase + (long)kt * NT * D_DIM);
            #pragma unroll
            for (int i = 0; i < 8; i++) {
                int idx = tid + i * 256;
                int row = idx >> 4, c4 = (idx & 15) << 2;
                float4 val = srck[idx];
                val.x = to_tf32(val.x); val.y = to_tf32(val.y);
                val.z = to_tf32(val.z); val.w = to_tf32(val.w);
                *reinterpret_cast<float4*>(ks + row * QSTR + c4) = val;
                float4 vv = srcv[idx];
                vv.x = to_tf32(vv.x); vv.y = to_tf32(vv.y);
                vv.z = to_tf32(vv.z); vv.w = to_tf32(vv.w);
                *reinterpret_cast<float4*>(vs + row * QSTR + c4) = vv;
            }
            if (tid < NT) msk[tid] = mbase[kt * NT + tid];
        }
        __syncthreads();

        float c[2][8][4];
        #pragma unroll
        for (int mi = 0; mi < 2; mi++)
            #pragma unroll
            for (int ni = 0; ni < 8; ni++)
                #pragma unroll
                for (int r = 0; r < 4; r++) c[mi][ni][r] = 0.f;

        #pragma unroll
        for (int kk = 0; kk < 64; kk += 8) {
            uint32_t bf[8][2];
            #pragma unroll
            for (int ni = 0; ni < 8; ni++) {
                int nr = wn * 64 + ni * 8 + g;
                bf[ni][0] = __float_as_uint(ks[nr * QSTR + kk + cq]);
                bf[ni][1] = __float_as_uint(ks[nr * QSTR + kk + 4 + cq]);
            }
            #pragma unroll
            for (int mi = 0; mi < 2; mi++) {
                int mr = wm * 32 + mi * 16;
                uint32_t a[4];
                a[0] = __float_as_uint(qs[(mr + g)     * QSTR + kk + cq]);
                a[1] = __float_as_uint(qs[(mr + g + 8) * QSTR + kk + cq]);
                a[2] = __float_as_uint(qs[(mr + g)     * QSTR + kk + 4 + cq]);
                a[3] = __float_as_uint(qs[(mr + g + 8) * QSTR + kk + 4 + cq]);
                #pragma unroll
                for (int ni = 0; ni < 8; ni++) mma8(c[mi][ni], a, bf[ni]);
            }
        }

        // P = exp(S)/rowsum : write attention (fp32) + stage P (tf32) in smem
        #pragma unroll
        for (int mi = 0; mi < 2; mi++) {
            int r0 = wm * 32 + mi * 16 + g;
            #pragma unroll
            for (int ni = 0; ni < 8; ni++) {
                int col = wn * 64 + ni * 8 + 2 * cq;
                int m0 = msk[col], m1 = msk[col + 1];
                float p0 = m0 ? __expf(c[mi][ni][0]) * inv[mi][0] : 0.f;
                float p1 = m1 ? __expf(c[mi][ni][1]) * inv[mi][0] : 0.f;
                float p2 = m0 ? __expf(c[mi][ni][2]) * inv[mi][1] : 0.f;
                float p3 = m1 ? __expf(c[mi][ni][3]) * inv[mi][1] : 0.f;
                *reinterpret_cast<float2*>(&ps[r0 * PSTR + col]) =
                    make_float2(to_tf32(p0), to_tf32(p1));
                *reinterpret_cast<float2*>(&ps[(r0 + 8) * PSTR + col]) =
                    make_float2(to_tf32(p2), to_tf32(p3));
                if (abase) {
                    *reinterpret_cast<float2*>(abase + (long)r0 * S_LEN + kt * NT + col) =
                        make_float2(p0, p1);
                    *reinterpret_cast<float2*>(abase + (long)(r0 + 8) * S_LEN + kt * NT + col) =
                        make_float2(p2, p3);
                }
            }
        }
        __syncthreads();

        // O += P[128x128] @ V[128x64]
        #pragma unroll
        for (int kk = 0; kk < 128; kk += 8) {
            uint32_t bv[4][2];
            #pragma unroll
            for (int ni = 0; ni < 4; ni++) {
                int dcol = wn * 32 + ni * 8 + g;
                bv[ni][0] = __float_as_uint(vs[(kk + cq)     * QSTR + dcol]);
                bv[ni][1] = __float_as_uint(vs[(kk + 4 + cq) * QSTR + dcol]);
            }
            #pragma unroll
            for (int mi = 0; mi < 2; mi++) {
                int mr = wm * 32 + mi * 16;
                uint32_t a[4];
                a[0] = __float_as_uint(ps[(mr + g)     * PSTR + kk + cq]);
                a[1] = __float_as_uint(ps[(mr + g + 8) * PSTR + kk + cq]);
                a[2] = __float_as_uint(ps[(mr + g)     * PSTR + kk + 4 + cq]);
                a[3] = __float_as_uint(ps[(mr + g + 8) * PSTR + kk + 4 + cq]);
                #pragma unroll
                for (int ni = 0; ni < 4; ni++) mma8(o[mi][ni], a, bv[ni]);
            }
        }
    }

    // ---- write O ----
    #pragma unroll
    for (int mi = 0; mi < 2; mi++) {
        int r0 = wm * 32 + mi * 16 + g;
        #pragma unroll
        for (int ni = 0; ni < 4; ni++) {
            int dcol = wn * 32 + ni * 8 + 2 * cq;
            *reinterpret_cast<float2*>(obase + (long)r0 * D_DIM + dcol) =
                make_float2(o[mi][ni][0], o[mi][ni][1]);
            *reinterpret_cast<float2*>(obase + (long)(r0 + 8) * D_DIM + dcol) =
                make_float2(o[mi][ni][2], o[mi][ni][3]);
        }
    }
}

extern "C" void kernel_launch(void* const* d_in, const int* in_sizes, int n_in,
                              void* d_out, int out_size) {
    const float* q    = (const float*)d_in[0];
    const float* k    = (const float*)d_in[1];
    const float* v    = (const float*)d_in[2];
    const int*   mask = (const int*)d_in[3];

    float* out  = (float*)d_out;
    const long OUT_ELEMS  = 2L * 16 * 2048 * 64;       // 4,194,304
    const long ATTN_ELEMS = 2L * 16 * 2048 * 2048;     // 134,217,728
    float* attn = ((long)out_size >= OUT_ELEMS + ATTN_ELEMS) ? out + OUT_ELEMS : nullptr;

    cudaFuncSetAttribute(attn_fused, cudaFuncAttributeMaxDynamicSharedMemorySize, SMEM_BYTES);
    attn_fused<<<dim3(16, 32), 256, SMEM_BYTES>>>(q, k, v, mask, out, attn);
}

// round 2
// speedup vs baseline: 1.2104x; 1.2104x over previous
#include <cuda_runtime.h>
#include <cstdint>

// ScaledDotProductAttention B=2,H=16,S=2048,D=64 fp32, TEMP=32.
// d_out = [output 2*16*2048*64][attention 2*16*2048*2048]
//
// R2: 512 threads/CTA (4x4 warp grid), cp.async double-buffered tiles,
// tf32-preprocessed K (interleaved) and V^T (interleaved) in __device__ scratch,
// Q fragments register-resident, all mma fragments loaded via LDS.64.

#define S_LEN 2048
#define D_DIM 64
#define QT    128
#define NT    128
#define KTILES 16
#define KSTR  72     // K tile smem stride (floats): 72/2 mod 16 == 4 -> conflict-free LDS.64
#define VSTR  136    // V^T tile stride: 136/2 mod 16 == 4
#define PSTR  136    // P tile stride
#define NTHREADS 512

// tf32-preprocessed scratch (module-static device arrays; no runtime alloc)
__device__ float KS_g[2L * 16 * 2048 * 64];   // [bh][s][icol(d)]
__device__ float VT_g[2L * 16 * 64 * 2048];   // [bh][d][icol8(s)]

__host__ __device__ __forceinline__ int icol(int c) {
    return (c & ~7) | ((c & 3) << 1) | ((c >> 2) & 1);
}

__device__ __forceinline__ float to_tf32(float x) {
    uint32_t u; asm("cvt.rna.tf32.f32 %0, %1;" : "=r"(u) : "f"(x));
    return __uint_as_float(u);
}
__device__ __forceinline__ uint32_t to_tf32u(float x) {
    uint32_t u; asm("cvt.rna.tf32.f32 %0, %1;" : "=r"(u) : "f"(x));
    return u;
}
__device__ __forceinline__ void cp16(uint32_t dst, const void* src) {
    asm volatile("cp.async.cg.shared.global [%0], [%1], 16;" :: "r"(dst), "l"(src));
}
#define CP_COMMIT() asm volatile("cp.async.commit_group;" ::: "memory")
#define CP_WAIT0()  asm volatile("cp.async.wait_group 0;" ::: "memory")

__device__ __forceinline__ void mma8(float c[4], const uint32_t a[4], const uint32_t b[2]) {
    asm volatile(
        "mma.sync.aligned.m16n8k8.row.col.f32.tf32.tf32.f32 "
        "{%0,%1,%2,%3}, {%4,%5,%6,%7}, {%8,%9}, {%0,%1,%2,%3};\n"
        : "+f"(c[0]), "+f"(c[1]), "+f"(c[2]), "+f"(c[3])
        : "r"(a[0]), "r"(a[1]), "r"(a[2]), "r"(a[3]),
          "r"(b[0]), "r"(b[1]));
}

// ---------------- preprocessing ----------------

// K -> KS_g: tf32(rna) with interleaved d-columns (per 8-block)
__global__ void prep_k(const float* __restrict__ k) {
    long i = (long)blockIdx.x * 256 + threadIdx.x;      // float4 index
    float4 v = reinterpret_cast<const float4*>(k)[i];
    long row = i >> 4;                                   // bh*2048 + s
    int c0 = (int)(i & 15) << 2;
    float* dst = KS_g + row * 64;
    dst[icol(c0 + 0)] = to_tf32(v.x);
    dst[icol(c0 + 1)] = to_tf32(v.y);
    dst[icol(c0 + 2)] = to_tf32(v.z);
    dst[icol(c0 + 3)] = to_tf32(v.w);
}

// V -> VT_g: transpose to [bh][d][s], tf32, s interleaved per 8-block
__global__ void prep_v(const float* __restrict__ v) {
    __shared__ float sm[64][65];
    int bh = blockIdx.y;
    int s0 = blockIdx.x * 64;
    const float* src = v + ((long)bh * S_LEN + s0) * 64;
    for (int i = threadIdx.x; i < 64 * 16; i += 256) {   // 64 rows x 16 float4
        int r = i >> 4, c4 = (i & 15) << 2;
        float4 val = reinterpret_cast<const float4*>(src)[i];
        sm[r][c4 + 0] = val.x; sm[r][c4 + 1] = val.y;
        sm[r][c4 + 2] = val.z; sm[r][c4 + 3] = val.w;
    }
    __syncthreads();
    float* dst = VT_g + (long)bh * 64 * S_LEN;
    for (int i = threadIdx.x; i < 64 * 64; i += 256) {
        int d = i >> 6, s = i & 63;
        dst[(long)d * S_LEN + s0 + icol(s)] = to_tf32(sm[s][d]);
    }
}

// ---------------- main fused kernel ----------------

__global__ __launch_bounds__(NTHREADS, 1)
void attn_main(const float* __restrict__ q, const int* __restrict__ mask,
               float* __restrict__ out, float* __restrict__ attn)
{
    extern __shared__ float smf[];
    float* ks     = smf;                       // 2 x 128 x 72
    float* vs     = ks + 2 * NT * KSTR;        // 2 x 64 x 136
    float* ps     = vs + 2 * 64 * VSTR;        // 128 x 136
    float* rowsum = ps + QT * PSTR;            // 512
    int*   msk    = (int*)(rowsum + 512);      // 2 x 128

    const int tid  = threadIdx.x;
    const int lane = tid & 31;
    const int w    = tid >> 5;
    const int wm   = w >> 2;        // 0..3 -> 32 rows
    const int wn   = w & 3;         // 0..3 -> 32 QK cols / 16 PV cols
    const int g    = lane >> 2;     // 0..7
    const int cq   = lane & 3;      // 0..3

    const int qt = blockIdx.x;      // 0..15
    const int bh = blockIdx.y;      // 0..31
    const int b  = bh >> 4;
    const int q0 = qt * QT;

    const float* kS = KS_g + (long)bh * S_LEN * 64;
    const float* vT = VT_g + (long)bh * 64 * S_LEN;
    const int* mbase = mask + (long)b * S_LEN;
    float* obase = out + ((long)bh * S_LEN + q0) * D_DIM;
    float* abase = attn ? attn + ((long)bh * S_LEN + q0) * (long)S_LEN : (float*)0;

    const uint32_t ks_sm  = (uint32_t)__cvta_generic_to_shared(ks);
    const uint32_t vs_sm  = (uint32_t)__cvta_generic_to_shared(vs);
    const uint32_t msk_sm = (uint32_t)__cvta_generic_to_shared(msk);

#define LOAD_K(buf_, kt_) do { \
        const float* s_ = kS + (long)(kt_) * NT * 64; \
        uint32_t d_ = ks_sm + (buf_) * NT * KSTR * 4; \
        _Pragma("unroll") \
        for (int i_ = 0; i_ < 4; i_++) { \
            int idx_ = tid + i_ * NTHREADS; \
            int r_ = idx_ >> 4, c_ = idx_ & 15; \
            cp16(d_ + (r_ * KSTR + c_ * 4) * 4, s_ + r_ * 64 + c_ * 4); \
        } \
        if (tid < 32) cp16(msk_sm + (buf_) * 128 * 4 + tid * 16, mbase + (kt_) * NT + tid * 4); \
    } while (0)

#define LOAD_V(buf_, kt_) do { \
        const float* s_ = vT + (long)(kt_) * NT; \
        uint32_t d_ = vs_sm + (buf_) * 64 * VSTR * 4; \
        _Pragma("unroll") \
        for (int i_ = 0; i_ < 4; i_++) { \
            int idx_ = tid + i_ * NTHREADS; \
            int r_ = idx_ >> 5, c_ = idx_ & 31; \
            cp16(d_ + (r_ * VSTR + c_ * 4) * 4, s_ + (long)r_ * S_LEN + c_ * 4); \
        } \
    } while (0)

    // prefetch tile 0 of K before anything else
    LOAD_K(0, 0);
    CP_COMMIT();

    // ---- Q fragments: register-resident for the whole kernel (tf32, scaled 1/32) ----
    uint32_t qf[2][8][4];
    {
        const float* qb = q + ((long)bh * S_LEN + q0 + wm * 32) * D_DIM;
        #pragma unroll
        for (int mi = 0; mi < 2; mi++) {
            const float* r0 = qb + (mi * 16 + g) * D_DIM;
            const float* r1 = r0 + 8 * D_DIM;
            #pragma unroll
            for (int blk = 0; blk < 8; blk++) {
                qf[mi][blk][0] = to_tf32u(r0[blk * 8 + cq]     * 0.03125f);
                qf[mi][blk][1] = to_tf32u(r1[blk * 8 + cq]     * 0.03125f);
                qf[mi][blk][2] = to_tf32u(r0[blk * 8 + 4 + cq] * 0.03125f);
                qf[mi][blk][3] = to_tf32u(r1[blk * 8 + 4 + cq] * 0.03125f);
            }
        }
    }

    // =========================== PASS 1: rowsums ===========================
    float rs[2][2] = {{0.f, 0.f}, {0.f, 0.f}};
    for (int kt = 0; kt < KTILES; kt++) {
        CP_WAIT0();
        __syncthreads();
        if (kt + 1 < KTILES) { LOAD_K((kt + 1) & 1, kt + 1); CP_COMMIT(); }

        const float* kb = ks + (kt & 1) * NT * KSTR;
        float c[2][4][4];
        #pragma unroll
        for (int mi = 0; mi < 2; mi++)
            #pragma unroll
            for (int ni = 0; ni < 4; ni++)
                #pragma unroll
                for (int r = 0; r < 4; r++) c[mi][ni][r] = 0.f;

        #pragma unroll
        for (int blk = 0; blk < 8; blk++) {
            uint32_t bf[4][2];
            #pragma unroll
            for (int ni = 0; ni < 4; ni++) {
                uint2 t = *reinterpret_cast<const uint2*>(
                    &kb[(wn * 32 + ni * 8 + g) * KSTR + blk * 8 + cq * 2]);
                bf[ni][0] = t.x; bf[ni][1] = t.y;
            }
            #pragma unroll
            for (int mi = 0; mi < 2; mi++)
                #pragma unroll
                for (int ni = 0; ni < 4; ni++) mma8(c[mi][ni], qf[mi][blk], bf[ni]);
        }

        const int* mb = msk + (kt & 1) * 128;
        #pragma unroll
        for (int ni = 0; ni < 4; ni++) {
            int col = wn * 32 + ni * 8 + 2 * cq;
            int m0 = mb[col], m1 = mb[col + 1];
            #pragma unroll
            for (int mi = 0; mi < 2; mi++) {
                rs[mi][0] += (m0 ? __expf(c[mi][ni][0]) : 0.f) + (m1 ? __expf(c[mi][ni][1]) : 0.f);
                rs[mi][1] += (m0 ? __expf(c[mi][ni][2]) : 0.f) + (m1 ? __expf(c[mi][ni][3]) : 0.f);
            }
        }
    }

    // deterministic reduction: lane(cq) -> warp partial -> combine 4 wn groups
    #pragma unroll
    for (int mi = 0; mi < 2; mi++)
        #pragma unroll
        for (int h = 0; h < 2; h++) {
            float s = rs[mi][h];
            s += __shfl_xor_sync(0xffffffffu, s, 1);
            s += __shfl_xor_sync(0xffffffffu, s, 2);
            if (cq == 0) rowsum[wn * 128 + wm * 32 + mi * 16 + h * 8 + g] = s;
        }
    __syncthreads();
    if (tid < 128) {
        float t = rowsum[tid] + rowsum[128 + tid] + rowsum[256 + tid] + rowsum[384 + tid];
        rowsum[tid] = 1.0f / t;
    }
    __syncthreads();
    float inv[2][2];
    #pragma unroll
    for (int mi = 0; mi < 2; mi++)
        #pragma unroll
        for (int h = 0; h < 2; h++)
            inv[mi][h] = rowsum[wm * 32 + mi * 16 + h * 8 + g];

    // ================== PASS 2: attention write + O = P V ==================
    LOAD_K(0, 0);
    LOAD_V(0, 0);
    CP_COMMIT();

    float o[2][2][4];
    #pragma unroll
    for (int mi = 0; mi < 2; mi++)
        #pragma unroll
        for (int ni = 0; ni < 2; ni++)
            #pragma unroll
            for (int r = 0; r < 4; r++) o[mi][ni][r] = 0.f;

    for (int kt = 0; kt < KTILES; kt++) {
        CP_WAIT0();
        __syncthreads();
        if (kt + 1 < KTILES) {
            LOAD_K((kt + 1) & 1, kt + 1);
            LOAD_V((kt + 1) & 1, kt + 1);
            CP_COMMIT();
        }

        // --- QK ---
        const float* kb = ks + (kt & 1) * NT * KSTR;
        float c[2][4][4];
        #pragma unroll
        for (int mi = 0; mi < 2; mi++)
            #pragma unroll
            for (int ni = 0; ni < 4; ni++)
                #pragma unroll
                for (int r = 0; r < 4; r++) c[mi][ni][r] = 0.f;

        #pragma unroll
        for (int blk = 0; blk < 8; blk++) {
            uint32_t bf[4][2];
            #pragma unroll
            for (int ni = 0; ni < 4; ni++) {
                uint2 t = *reinterpret_cast<const uint2*>(
                    &kb[(wn * 32 + ni * 8 + g) * KSTR + blk * 8 + cq * 2]);
                bf[ni][0] = t.x; bf[ni][1] = t.y;
            }
            #pragma unroll
            for (int mi = 0; mi < 2; mi++)
                #pragma unroll
                for (int ni = 0; ni < 4; ni++) mma8(c[mi][ni], qf[mi][blk], bf[ni]);
        }

        // --- P = exp(S)*inv: write attention + stage P (interleaved tf32) ---
        const int* mb = msk + (kt & 1) * 128;
        #pragma unroll
        for (int ni = 0; ni < 4; ni++) {
            int col = wn * 32 + ni * 8 + 2 * cq;
            int m0 = mb[col], m1 = mb[col + 1];
            int ic0 = icol(col), ic1 = icol(col + 1);
            #pragma unroll
            for (int mi = 0; mi < 2; mi++) {
                int r0 = wm * 32 + mi * 16 + g;
                float p0 = m0 ? __expf(c[mi][ni][0]) * inv[mi][0] : 0.f;
                float p1 = m1 ? __expf(c[mi][ni][1]) * inv[mi][0] : 0.f;
                float p2 = m0 ? __expf(c[mi][ni][2]) * inv[mi][1] : 0.f;
                float p3 = m1 ? __expf(c[mi][ni][3]) * inv[mi][1] : 0.f;
                ps[r0 * PSTR + ic0] = to_tf32(p0);
                ps[r0 * PSTR + ic1] = to_tf32(p1);
                ps[(r0 + 8) * PSTR + ic0] = to_tf32(p2);
                ps[(r0 + 8) * PSTR + ic1] = to_tf32(p3);
                if (abase) {
                    *reinterpret_cast<float2*>(abase + (long)r0 * S_LEN + kt * NT + col) =
                        make_float2(p0, p1);
                    *reinterpret_cast<float2*>(abase + (long)(r0 + 8) * S_LEN + kt * NT + col) =
                        make_float2(p2, p3);
                }
            }
        }
        __syncthreads();

        // --- O += P @ V ---
        const float* vb = vs + (kt & 1) * 64 * VSTR;
        #pragma unroll
        for (int blk = 0; blk < 16; blk++) {
            uint32_t bv[2][2];
            #pragma unroll
            for (int ni = 0; ni < 2; ni++) {
                uint2 t = *reinterpret_cast<const uint2*>(
                    &vb[(wn * 16 + ni * 8 + g) * VSTR + blk * 8 + cq * 2]);
                bv[ni][0] = t.x; bv[ni][1] = t.y;
            }
            #pragma unroll
            for (int mi = 0; mi < 2; mi++) {
                uint2 lo = *reinterpret_cast<const uint2*>(
                    &ps[(wm * 32 + mi * 16 + g) * PSTR + blk * 8 + cq * 2]);
                uint2 hi = *reinterpret_cast<const uint2*>(
                    &ps[(wm * 32 + mi * 16 + g + 8) * PSTR + blk * 8 + cq * 2]);
                uint32_t a[4] = {lo.x, hi.x, lo.y, hi.y};
                #pragma unroll
                for (int ni = 0; ni < 2; ni++) mma8(o[mi][ni], a, bv[ni]);
            }
        }
    }

    // ---- write O ----
    #pragma unroll
    for (int mi = 0; mi < 2; mi++) {
        int r0 = wm * 32 + mi * 16 + g;
        #pragma unroll
        for (int ni = 0; ni < 2; ni++) {
            int dc = wn * 16 + ni * 8 + 2 * cq;
            *reinterpret_cast<float2*>(obase + (long)r0 * D_DIM + dc) =
                make_float2(o[mi][ni][0], o[mi][ni][1]);
            *reinterpret_cast<float2*>(obase + (long)(r0 + 8) * D_DIM + dc) =
                make_float2(o[mi][ni][2], o[mi][ni][3]);
        }
    }
#undef LOAD_K
#undef LOAD_V
}

extern "C" void kernel_launch(void* const* d_in, const int* in_sizes, int n_in,
                              void* d_out, int out_size) {
    const float* q    = (const float*)d_in[0];
    const float* k    = (const float*)d_in[1];
    const float* v    = (const float*)d_in[2];
    const int*   mask = (const int*)d_in[3];

    float* out = (float*)d_out;
    const long OUT_ELEMS  = 2L * 16 * 2048 * 64;
    const long ATTN_ELEMS = 2L * 16 * 2048 * 2048;
    float* attn = ((long)out_size >= OUT_ELEMS + ATTN_ELEMS) ? out + OUT_ELEMS : nullptr;

    // preprocess K (tf32, interleaved) and V (transpose + tf32, interleaved)
    prep_k<<<4096, 256>>>(k);
    prep_v<<<dim3(32, 32), 256>>>(v);

    const int smem_bytes = (2 * NT * KSTR + 2 * 64 * VSTR + QT * PSTR + 512) * 4 + 2 * 128 * 4;
    cudaFuncSetAttribute(attn_main, cudaFuncAttributeMaxDynamicSharedMemorySize, smem_bytes);
    attn_main<<<dim3(16, 32), NTHREADS, smem_bytes>>>(q, mask, out, attn);
}

// round 4
// speedup vs baseline: 1.6212x; 1.3393x over previous
#include <cuda_runtime.h>
#include <cuda_fp16.h>
#include <cstdint>

// ScaledDotProductAttention B=2,H=16,S=2048,D=64 fp32, TEMP=32.
// d_out = [output 2*16*2048*64][attention 2*16*2048*2048]
//
// R4 (legacy mma only; tcgen05 unsupported by harness ptxas target):
//  - fp16 m16n8k16 mma for QK and PV (same 10 mantissa bits as tf32, half the instrs)
//  - SINGLE pass: PV runs on unnormalized exp(S); invr applied to O at end.
//  - unnormalized exp(S) tiles staged fp16 in __device__ scratch; in-kernel tail
//    streams scratch (mostly L2-resident) -> normalized fp32 attention.

#define S_LEN 2048
#define KTILES 16
#define NTHREADS 512
#define KSTR 80     // halfs; 160B row stride (== 32 mod 128 -> conflict-free LDS.64)
#define VSTR 144    // halfs; 288B
#define PSTR 144

// smem byte offsets
#define KOFF   0         // 2 x 128 x 160B = 40960
#define VOFF   40960     // 2 x 64 x 288B  = 36864
#define POFF   77824     // 128 x 288B     = 36864
#define REDOFF 114688    // 512 floats
#define INVOFF 116736    // 128 floats
#define MBOFF  117248    // 64 u32
#define SMEM_TOTAL 117504

__device__ __half KH_g[2L * 16 * 2048 * 64];     // K fp16, d 16-interleaved
__device__ __half VTH_g[2L * 16 * 64 * 2048];    // V^T fp16, s 16-interleaved
__device__ __half SCR_g[2L * 16 * 2048 * 2048];  // unnormalized exp(S), interleaved

// physical position of logical col c within its 16-block (pairs (2c,2c+1),(2c+8,+9) adjacent)
__host__ __device__ __forceinline__ int p16(int c) {
    return (c & ~15) | ((c & 6) << 1) | (c & 1) | ((c & 8) >> 2);
}

__device__ __forceinline__ uint32_t packh2(float a, float b) {
    __half2 h = __floats2half2_rn(a, b);
    return *reinterpret_cast<uint32_t*>(&h);
}

__device__ __forceinline__ void cp16(uint32_t dst, const void* src) {
    asm volatile("cp.async.cg.shared.global [%0], [%1], 16;" :: "r"(dst), "l"(src));
}
#define CP_COMMIT() asm volatile("cp.async.commit_group;" ::: "memory")
#define CP_WAIT0()  asm volatile("cp.async.wait_group 0;" ::: "memory")

__device__ __forceinline__ void mma16(float c[4], const uint32_t a[4], const uint32_t b[2]) {
    asm volatile(
        "mma.sync.aligned.m16n8k16.row.col.f32.f16.f16.f32 "
        "{%0,%1,%2,%3}, {%4,%5,%6,%7}, {%8,%9}, {%0,%1,%2,%3};\n"
        : "+f"(c[0]), "+f"(c[1]), "+f"(c[2]), "+f"(c[3])
        : "r"(a[0]), "r"(a[1]), "r"(a[2]), "r"(a[3]),
          "r"(b[0]), "r"(b[1]));
}

// ---------------- preprocessing ----------------

// K fp32 -> KH_g fp16, d interleaved per 16-block
__global__ void prep_k(const float* __restrict__ k) {
    long i = (long)blockIdx.x * 256 + threadIdx.x;   // float4 idx, 1M total
    float4 v = reinterpret_cast<const float4*>(k)[i];
    long row = i >> 4;
    int c0 = (int)(i & 15) << 2;
    __half* dst = KH_g + row * 64;
    *reinterpret_cast<uint32_t*>(dst + p16(c0))     = packh2(v.x, v.y);
    *reinterpret_cast<uint32_t*>(dst + p16(c0 + 2)) = packh2(v.z, v.w);
}

// V fp32 [bh][s][64] -> VTH_g fp16 [bh][d][2048], s interleaved per 16-block
__global__ void prep_v(const float* __restrict__ v) {
    __shared__ float sm[64][65];
    int bh = blockIdx.y;
    int s0 = blockIdx.x * 64;
    const float4* src = reinterpret_cast<const float4*>(v + ((long)bh * S_LEN + s0) * 64);
    for (int i = threadIdx.x; i < 64 * 16; i += 256) {
        int r = i >> 4, c4 = (i & 15) << 2;
        float4 val = src[i];
        sm[r][c4 + 0] = val.x; sm[r][c4 + 1] = val.y;
        sm[r][c4 + 2] = val.z; sm[r][c4 + 3] = val.w;
    }
    __syncthreads();
    __half* dst = VTH_g + (long)bh * 64 * S_LEN;
    for (int i = threadIdx.x; i < 64 * 16; i += 256) {
        int d = i >> 4, sl4 = (i & 15) << 2;
        __half* drow = dst + (long)d * S_LEN + s0;
        *reinterpret_cast<uint32_t*>(drow + p16(sl4)) =
            packh2(sm[sl4 + 0][d], sm[sl4 + 1][d]);
        *reinterpret_cast<uint32_t*>(drow + p16(sl4 + 2)) =
            packh2(sm[sl4 + 2][d], sm[sl4 + 3][d]);
    }
}

// ---------------- main fused kernel ----------------

__global__ __launch_bounds__(NTHREADS, 1)
void attn_main(const float* __restrict__ q, const int* __restrict__ mask,
               float* __restrict__ out, float* __restrict__ attn)
{
    extern __shared__ char smc[];
    __half* ksh = (__half*)(smc + KOFF);
    __half* vsh = (__half*)(smc + VOFF);
    __half* psh = (__half*)(smc + POFF);
    float*  red = (float*)(smc + REDOFF);
    float*  inv_s = (float*)(smc + INVOFF);
    uint32_t* mbits = (uint32_t*)(smc + MBOFF);
    const uint32_t smb = (uint32_t)__cvta_generic_to_shared(smc);

    const int tid  = threadIdx.x;
    const int lane = tid & 31;
    const int w    = tid >> 5;
    const int wm   = w >> 2;          // 0..3 -> 32 q-rows
    const int wn   = w & 3;           // 0..3 -> 32 s-cols (QK) / 16 d-cols (PV)
    const int g    = lane >> 2;
    const int cq   = lane & 3;

    const int qt = blockIdx.x, bh = blockIdx.y;
    const int b = bh >> 4, q0 = qt * 128;

    const __half* kH = KH_g + (long)bh * S_LEN * 64;
    const __half* vT = VTH_g + (long)bh * 64 * S_LEN;
    const int* mbase = mask + (long)b * S_LEN;
    float* obase = out + ((long)bh * S_LEN + q0) * 64;
    float* abase = attn ? attn + ((long)bh * S_LEN + q0) * (long)S_LEN : (float*)0;
    __half* scr  = SCR_g + ((long)bh * 16 + qt) * (16L * 16384);

#define LOAD_K(buf_, kt_) do { \
        const __half* s_ = kH + (long)(kt_) * 128 * 64; \
        uint32_t d_ = smb + KOFF + (buf_) * 20480; \
        _Pragma("unroll") \
        for (int i_ = 0; i_ < 2; i_++) { \
            int idx_ = tid + i_ * NTHREADS; \
            int r_ = idx_ >> 3, c_ = idx_ & 7; \
            cp16(d_ + r_ * 160 + c_ * 16, s_ + r_ * 64 + c_ * 8); \
        } \
    } while (0)

#define LOAD_V(buf_, kt_) do { \
        const __half* s_ = vT + (kt_) * 128; \
        uint32_t d_ = smb + VOFF + (buf_) * 18432; \
        _Pragma("unroll") \
        for (int i_ = 0; i_ < 2; i_++) { \
            int idx_ = tid + i_ * NTHREADS; \
            int r_ = idx_ >> 4, c_ = idx_ & 15; \
            cp16(d_ + r_ * 288 + c_ * 16, s_ + (long)r_ * S_LEN + c_ * 8); \
        } \
    } while (0)

    LOAD_K(0, 0);
    LOAD_V(0, 0);
    CP_COMMIT();

    // mask ballot words: mbits[t*4+grp] bit j <-> col grp*32+j of tile t
    if (w < 4) {
        for (int t = 0; t < KTILES; t++) {
            int mv = mbase[t * 128 + w * 32 + lane];
            uint32_t bits = __ballot_sync(0xffffffffu, mv != 0);
            if (lane == 0) mbits[t * 4 + w] = bits;
        }
    }

    // Q fragments, fp16, scaled 1/32, register-resident
    uint32_t qf[2][4][4];
    {
        const float* qb = q + ((long)bh * S_LEN + q0 + wm * 32) * 64;
        #pragma unroll
        for (int mi = 0; mi < 2; mi++) {
            const float* r0p = qb + (mi * 16 + g) * 64;
            const float* r1p = r0p + 8 * 64;
            #pragma unroll
            for (int blk = 0; blk < 4; blk++) {
                int c0 = blk * 16 + 2 * cq;
                qf[mi][blk][0] = packh2(r0p[c0] * 0.03125f,     r0p[c0 + 1] * 0.03125f);
                qf[mi][blk][1] = packh2(r1p[c0] * 0.03125f,     r1p[c0 + 1] * 0.03125f);
                qf[mi][blk][2] = packh2(r0p[c0 + 8] * 0.03125f, r0p[c0 + 9] * 0.03125f);
                qf[mi][blk][3] = packh2(r1p[c0 + 8] * 0.03125f, r1p[c0 + 9] * 0.03125f);
            }
        }
    }

    float rs[2][2] = {{0.f, 0.f}, {0.f, 0.f}};
    float o[2][2][4];
    #pragma unroll
    for (int mi = 0; mi < 2; mi++)
        #pragma unroll
        for (int ni = 0; ni < 2; ni++)
            #pragma unroll
            for (int r = 0; r < 4; r++) o[mi][ni][r] = 0.f;

    for (int kt = 0; kt < KTILES; kt++) {
        CP_WAIT0();
        __syncthreads();
        int cb = kt & 1;
        if (kt + 1 < KTILES) {
            int nb = (kt + 1) & 1;
            LOAD_K(nb, kt + 1);
            LOAD_V(nb, kt + 1);
            CP_COMMIT();
        }

        // ---- S = (Q/32) K^T ----
        const __half* kb_ = ksh + cb * 128 * KSTR;
        float c[2][4][4];
        #pragma unroll
        for (int mi = 0; mi < 2; mi++)
            #pragma unroll
            for (int ni = 0; ni < 4; ni++)
                #pragma unroll
                for (int r = 0; r < 4; r++) c[mi][ni][r] = 0.f;

        #pragma unroll
        for (int blk = 0; blk < 4; blk++) {
            uint32_t bf[4][2];
            #pragma unroll
            for (int ni = 0; ni < 4; ni++) {
                uint2 t = *reinterpret_cast<const uint2*>(
                    kb_ + (wn * 32 + ni * 8 + g) * KSTR + blk * 16 + cq * 4);
                bf[ni][0] = t.x; bf[ni][1] = t.y;
            }
            #pragma unroll
            for (int mi = 0; mi < 2; mi++)
                #pragma unroll
                for (int ni = 0; ni < 4; ni++) mma16(c[mi][ni], qf[mi][blk], bf[ni]);
        }

        // ---- epilogue: e = exp(S) (masked), rowsum accum, stage fp16 P ----
        uint32_t word = mbits[kt * 4 + wn];
        #pragma unroll
        for (int ni = 0; ni < 4; ni++) {
            int j = ni * 8 + 2 * cq;
            int m0 = (word >> j) & 1, m1 = (word >> (j + 1)) & 1;
            int col = wn * 32 + j;
            int phys = (col & ~15) | ((2 * cq) << 1) | ((ni & 1) << 1);  // col even
            #pragma unroll
            for (int mi = 0; mi < 2; mi++) {
                int r0 = wm * 32 + mi * 16 + g;
                float e0 = m0 ? __expf(c[mi][ni][0]) : 0.f;
                float e1 = m1 ? __expf(c[mi][ni][1]) : 0.f;
                float e2 = m0 ? __expf(c[mi][ni][2]) : 0.f;
                float e3 = m1 ? __expf(c[mi][ni][3]) : 0.f;
                rs[mi][0] += e0 + e1;
                rs[mi][1] += e2 + e3;
                *reinterpret_cast<uint32_t*>(psh + r0 * PSTR + phys)       = packh2(e0, e1);
                *reinterpret_cast<uint32_t*>(psh + (r0 + 8) * PSTR + phys) = packh2(e2, e3);
            }
        }
        __syncthreads();

        // ---- O += P_unnorm @ V ----
        const __half* vb = vsh + cb * 64 * VSTR;
        #pragma unroll
        for (int kb = 0; kb < 8; kb++) {
            uint32_t bv[2][2];
            #pragma unroll
            for (int ni = 0; ni < 2; ni++) {
                uint2 t = *reinterpret_cast<const uint2*>(
                    vb + (wn * 16 + ni * 8 + g) * VSTR + kb * 16 + cq * 4);
                bv[ni][0] = t.x; bv[ni][1] = t.y;
            }
            #pragma unroll
            for (int mi = 0; mi < 2; mi++) {
                uint2 lo = *reinterpret_cast<const uint2*>(
                    psh + (wm * 32 + mi * 16 + g) * PSTR + kb * 16 + cq * 4);
                uint2 hi = *reinterpret_cast<const uint2*>(
                    psh + (wm * 32 + mi * 16 + g + 8) * PSTR + kb * 16 + cq * 4);
                uint32_t a[4] = {lo.x, hi.x, lo.y, hi.y};
                #pragma unroll
                for (int ni = 0; ni < 2; ni++) mma16(o[mi][ni], a, bv[ni]);
            }
        }

        // ---- stage unnormalized exp tile to global scratch (coalesced) ----
        if (abase) {
            __half* sd = scr + (long)kt * 16384;
            #pragma unroll
            for (int i2 = 0; i2 < 4; i2++) {
                int f = tid + i2 * NTHREADS;         // 2048 x 16B
                int r = f >> 4, cc = f & 15;
                *reinterpret_cast<uint4*>(sd + f * 8) =
                    *reinterpret_cast<const uint4*>(
                        reinterpret_cast<const char*>(psh) + r * 288 + cc * 16);
            }
        }
        __syncthreads();
    }

    // ---- rowsum reduce -> invr ----
    #pragma unroll
    for (int mi = 0; mi < 2; mi++)
        #pragma unroll
        for (int h = 0; h < 2; h++) {
            float s = rs[mi][h];
            s += __shfl_xor_sync(0xffffffffu, s, 1);
            s += __shfl_xor_sync(0xffffffffu, s, 2);
            if (cq == 0) red[wn * 128 + wm * 32 + mi * 16 + h * 8 + g] = s;
        }
    __syncthreads();
    if (tid < 128) {
        float t = red[tid] + red[128 + tid] + red[256 + tid] + red[384 + tid];
        inv_s[tid] = 1.0f / t;
    }
    __syncthreads();

    // ---- write O = O_unnorm * invr ----
    {
        float inv[2][2];
        #pragma unroll
        for (int mi = 0; mi < 2; mi++)
            #pragma unroll
            for (int h = 0; h < 2; h++)
                inv[mi][h] = inv_s[wm * 32 + mi * 16 + h * 8 + g];
        #pragma unroll
        for (int mi = 0; mi < 2; mi++) {
            int r0 = wm * 32 + mi * 16 + g;
            #pragma unroll
            for (int ni = 0; ni < 2; ni++) {
                int dc = wn * 16 + ni * 8 + 2 * cq;
                *reinterpret_cast<float2*>(obase + (long)r0 * 64 + dc) =
                    make_float2(o[mi][ni][0] * inv[mi][0], o[mi][ni][1] * inv[mi][0]);
                *reinterpret_cast<float2*>(obase + (long)(r0 + 8) * 64 + dc) =
                    make_float2(o[mi][ni][2] * inv[mi][1], o[mi][ni][3] * inv[mi][1]);
            }
        }
    }

    // ---- tail: scratch (fp16, L2-warm) -> normalized fp32 attention ----
    if (abase) {
        for (int kt = 0; kt < KTILES; kt++) {
            const __half* ss = scr + (long)kt * 16384;
            #pragma unroll
            for (int i2 = 0; i2 < 2; i2++) {
                int idx = tid + i2 * NTHREADS;       // 1024 16-half blocks
                int r = idx >> 3, blk = idx & 7;
                float iv = inv_s[r];
                uint4 u0 = *reinterpret_cast<const uint4*>(ss + idx * 16);
                uint4 u1 = *reinterpret_cast<const uint4*>(ss + idx * 16 + 8);
                float2 f0 = __half22float2(*reinterpret_cast<__half2*>(&u0.x));
                float2 f1 = __half22float2(*reinterpret_cast<__half2*>(&u0.y));
                float2 f2 = __half22float2(*reinterpret_cast<__half2*>(&u0.z));
                float2 f3 = __half22float2(*reinterpret_cast<__half2*>(&u0.w));
                float2 f4 = __half22float2(*reinterpret_cast<__half2*>(&u1.x));
                float2 f5 = __half22float2(*reinterpret_cast<__half2*>(&u1.y));
                float2 f6 = __half22float2(*reinterpret_cast<__half2*>(&u1.z));
                float2 f7 = __half22float2(*reinterpret_cast<__half2*>(&u1.w));
                float4* dst = reinterpret_cast<float4*>(
                    abase + (long)r * S_LEN + kt * 128 + blk * 16);
                dst[0] = make_float4(f0.x * iv, f0.y * iv, f2.x * iv, f2.y * iv);
                dst[1] = make_float4(f4.x * iv, f4.y * iv, f6.x * iv, f6.y * iv);
                dst[2] = make_float4(f1.x * iv, f1.y * iv, f3.x * iv, f3.y * iv);
                dst[3] = make_float4(f5.x * iv, f5.y * iv, f7.x * iv, f7.y * iv);
            }
        }
    }
#undef LOAD_K
#undef LOAD_V
}

extern "C" void kernel_launch(void* const* d_in, const int* in_sizes, int n_in,
                              void* d_out, int out_size) {
    const float* q    = (const float*)d_in[0];
    const float* k    = (const float*)d_in[1];
    const float* v    = (const float*)d_in[2];
    const int*   mask = (const int*)d_in[3];

    float* out = (float*)d_out;
    const long OUT_ELEMS  = 2L * 16 * 2048 * 64;
    const long ATTN_ELEMS = 2L * 16 * 2048 * 2048;
    float* attn = ((long)out_size >= OUT_ELEMS + ATTN_ELEMS) ? out + OUT_ELEMS : nullptr;

    prep_k<<<4096, 256>>>(k);
    prep_v<<<dim3(32, 32), 256>>>(v);

    cudaFuncSetAttribute(attn_main, cudaFuncAttributeMaxDynamicSharedMemorySize, SMEM_TOTAL);
    attn_main<<<dim3(16, 32), NTHREADS, SMEM_TOTAL>>>(q, mask, out, attn);
}